// round 10
// baseline (speedup 1.0000x reference)
#include <cuda_runtime.h>

#define NH   10
#define NL   10
#define TPB  128
#define PPT  4

// ---- raw weight layout in cw (float offsets) ----
#define OFF_W0   0
#define OFF_B0   30
#define OFF_W1   40
#define OFF_B1   140
#define OFF_WR1  150
#define OFF_BR1  1150
#define OFF_WR2  1250
#define OFF_BR2  2250
#define OFF_WR3  2350
#define OFF_BR3  3350
#define OFF_W8   3450
#define OFF_B8   3550
#define OFF_W9   3560
#define OFF_B9   3570
#define CW_TOTAL 3572

// ---- k-pair-packed table (float offsets, all float4-aligned) ----
// matrices: [k2][j][2] with element (k2,j,s) = W[2*k2+s][j]
// biases:   [j][2] = (b_j, 0)
#define KP_W0    0       // padded K=4: [2][10][2] -> 40
#define KP_B0    40      // 20
#define KP_W1    60      // 100
#define KP_B1    160     // 20
#define KP_RES   180
#define LSTR     340
#define KP_R1(l)  (KP_RES + (l)*LSTR)         // W1res  100
#define KP_B1R(l) (KP_RES + (l)*LSTR + 100)   // B1res  20
#define KP_W2(l)  (KP_RES + (l)*LSTR + 120)   // W2     100
#define KP_W3(l)  (KP_RES + (l)*LSTR + 220)   // W3     100
#define KP_B23(l) (KP_RES + (l)*LSTR + 320)   // B2+B3  20
#define KP_W8    3580    // 100
#define KP_B8    3680    // 20
#define KP_W9    3700    // [5][1][2] -> 10 (identity layout)
#define KP_B9    3710
#define KP_TOT   3712

__constant__ __align__(16) float cw[CW_TOTAL];
__constant__ __align__(16) float ckp[KP_TOT];
__device__   __align__(16) float kpbuf[KP_TOT];

__device__ __forceinline__ float2 f2(float x, float y) { return make_float2(x, y); }

// packed fp32x2 FMA (Blackwell FFMA2)
__device__ __forceinline__ float2 ffma2(float2 a, float2 b, float2 c) {
    float2 d;
    asm("{\n\t"
        ".reg .b64 ra, rb, rc, rd;\n\t"
        "mov.b64 ra, {%2, %3};\n\t"
        "mov.b64 rb, {%4, %5};\n\t"
        "mov.b64 rc, {%6, %7};\n\t"
        "fma.rn.f32x2 rd, ra, rb, rc;\n\t"
        "mov.b64 {%0, %1}, rd;\n\t"
        "}"
        : "=f"(d.x), "=f"(d.y)
        : "f"(a.x), "f"(a.y), "f"(b.x), "f"(b.y), "f"(c.x), "f"(c.y));
    return d;
}

// dense + relu, k-pair packed: out[p][j] = relu( sum_k h[p][k]*W[k][j] + B[j] )
// All reads of h complete before out is written -> in-place safe (out may alias h).
template<int K2>
__device__ __forceinline__ void dense_kp(const float* __restrict__ sw_, int Wo, int Bo,
                                         const float (&h)[PPT][2*K2], float (&out)[PPT][NH])
{
    float2 acc[PPT][NH];
#pragma unroll
    for (int j2 = 0; j2 < 5; j2++) {               // k2 = 0, bias (b,0) as addend
        float4 w = *(const float4*)(sw_ + Wo + j2*4);
        float4 b = *(const float4*)(sw_ + Bo + j2*4);
#pragma unroll
        for (int p = 0; p < PPT; p++) {
            acc[p][2*j2+0] = ffma2(f2(h[p][0], h[p][1]), f2(w.x, w.y), f2(b.x, b.y));
            acc[p][2*j2+1] = ffma2(f2(h[p][0], h[p][1]), f2(w.z, w.w), f2(b.z, b.w));
        }
    }
#pragma unroll
    for (int k2 = 1; k2 < K2; k2++) {
#pragma unroll
        for (int j2 = 0; j2 < 5; j2++) {
            float4 w = *(const float4*)(sw_ + Wo + k2*20 + j2*4);
#pragma unroll
            for (int p = 0; p < PPT; p++) {
                acc[p][2*j2+0] = ffma2(f2(h[p][2*k2], h[p][2*k2+1]), f2(w.x, w.y), acc[p][2*j2+0]);
                acc[p][2*j2+1] = ffma2(f2(h[p][2*k2], h[p][2*k2+1]), f2(w.z, w.w), acc[p][2*j2+1]);
            }
        }
    }
#pragma unroll
    for (int p = 0; p < PPT; p++)
#pragma unroll
        for (int j = 0; j < NH; j++)
            out[p][j] = fmaxf(acc[p][j].x + acc[p][j].y, 0.0f);
}

// residual: h0 <- relu( h1 @ W3 + h0 @ W2 + (B2+B3) ), k-pair packed, in-place on h0
__device__ __forceinline__ void dense_res_kp(const float* __restrict__ sw_,
                                             int W3o, int W2o, int B23o,
                                             const float (&h1)[PPT][NH], float (&h0)[PPT][NH])
{
    float2 acc[PPT][NH];
#pragma unroll
    for (int j2 = 0; j2 < 5; j2++) {               // k2 = 0 of W3, bias as addend
        float4 w = *(const float4*)(sw_ + W3o + j2*4);
        float4 b = *(const float4*)(sw_ + B23o + j2*4);
#pragma unroll
        for (int p = 0; p < PPT; p++) {
            acc[p][2*j2+0] = ffma2(f2(h1[p][0], h1[p][1]), f2(w.x, w.y), f2(b.x, b.y));
            acc[p][2*j2+1] = ffma2(f2(h1[p][0], h1[p][1]), f2(w.z, w.w), f2(b.z, b.w));
        }
    }
#pragma unroll
    for (int k2 = 1; k2 < 5; k2++) {
#pragma unroll
        for (int j2 = 0; j2 < 5; j2++) {
            float4 w = *(const float4*)(sw_ + W3o + k2*20 + j2*4);
#pragma unroll
            for (int p = 0; p < PPT; p++) {
                acc[p][2*j2+0] = ffma2(f2(h1[p][2*k2], h1[p][2*k2+1]), f2(w.x, w.y), acc[p][2*j2+0]);
                acc[p][2*j2+1] = ffma2(f2(h1[p][2*k2], h1[p][2*k2+1]), f2(w.z, w.w), acc[p][2*j2+1]);
            }
        }
    }
#pragma unroll
    for (int k2 = 0; k2 < 5; k2++) {
#pragma unroll
        for (int j2 = 0; j2 < 5; j2++) {
            float4 w = *(const float4*)(sw_ + W2o + k2*20 + j2*4);
#pragma unroll
            for (int p = 0; p < PPT; p++) {
                acc[p][2*j2+0] = ffma2(f2(h0[p][2*k2], h0[p][2*k2+1]), f2(w.x, w.y), acc[p][2*j2+0]);
                acc[p][2*j2+1] = ffma2(f2(h0[p][2*k2], h0[p][2*k2+1]), f2(w.z, w.w), acc[p][2*j2+1]);
            }
        }
    }
#pragma unroll
    for (int p = 0; p < PPT; p++)
#pragma unroll
        for (int j = 0; j < NH; j++)
            h0[p][j] = fmaxf(acc[p][j].x + acc[p][j].y, 0.0f);
}

// build the k-pair-interleaved table from raw weights
__global__ void prep_kernel()
{
    const int tid = threadIdx.x, bd = blockDim.x;
    // W0 padded to K=4
    for (int i = tid; i < 40; i += bd) {
        int k2 = i/20, j = (i%20)/2, s = i&1, r = 2*k2+s;
        kpbuf[KP_W0+i] = (r < 3) ? cw[OFF_W0 + r*10 + j] : 0.0f;
    }
    for (int i = tid; i < 20; i += bd)
        kpbuf[KP_B0+i] = (i&1) ? 0.0f : cw[OFF_B0 + i/2];
    for (int i = tid; i < 100; i += bd) {
        int k2 = i/20, j = (i%20)/2, s = i&1;
        kpbuf[KP_W1+i] = cw[OFF_W1 + (2*k2+s)*10 + j];
    }
    for (int i = tid; i < 20; i += bd)
        kpbuf[KP_B1+i] = (i&1) ? 0.0f : cw[OFF_B1 + i/2];
    for (int l = 0; l < NL; l++) {
        for (int i = tid; i < 100; i += bd) {
            int k2 = i/20, j = (i%20)/2, s = i&1, r = 2*k2+s;
            kpbuf[KP_R1(l)+i] = cw[OFF_WR1 + l*100 + r*10 + j];
            kpbuf[KP_W2(l)+i] = cw[OFF_WR2 + l*100 + r*10 + j];
            kpbuf[KP_W3(l)+i] = cw[OFF_WR3 + l*100 + r*10 + j];
        }
        for (int i = tid; i < 20; i += bd) {
            kpbuf[KP_B1R(l)+i] = (i&1) ? 0.0f : cw[OFF_BR1 + l*10 + i/2];
            kpbuf[KP_B23(l)+i] = (i&1) ? 0.0f :
                (cw[OFF_BR2 + l*10 + i/2] + cw[OFF_BR3 + l*10 + i/2]);
        }
    }
    for (int i = tid; i < 100; i += bd) {
        int k2 = i/20, j = (i%20)/2, s = i&1;
        kpbuf[KP_W8+i] = cw[OFF_W8 + (2*k2+s)*10 + j];
    }
    for (int i = tid; i < 20; i += bd)
        kpbuf[KP_B8+i] = (i&1) ? 0.0f : cw[OFF_B8 + i/2];
    for (int i = tid; i < 10; i += bd)
        kpbuf[KP_W9+i] = cw[OFF_W9 + i];        // [k2][1][2] is identity layout
    if (tid == 0) { kpbuf[KP_B9] = cw[OFF_B9]; kpbuf[KP_B9+1] = 0.0f; }
}

__global__ void __launch_bounds__(TPB, 3)
resnet_kernel(const float4* __restrict__ x4, float4* __restrict__ out4, int nthreads)
{
    __shared__ __align__(16) float sw_[KP_TOT];
    for (int i = threadIdx.x; i < KP_TOT/4; i += TPB)
        ((float4*)sw_)[i] = ((const float4*)ckp)[i];
    __syncthreads();

    int t = blockIdx.x * TPB + threadIdx.x;
    if (t >= nthreads) return;

    // 4 points = 12 contiguous floats = 3 aligned float4 loads
    float4 a = x4[3*t + 0];
    float4 b = x4[3*t + 1];
    float4 c = x4[3*t + 2];
    float xin[PPT][4] = {
        {a.x, a.y, a.z, 0.0f},
        {a.w, b.x, b.y, 0.0f},
        {b.z, b.w, c.x, 0.0f},
        {c.y, c.z, c.w, 0.0f}
    };

    float h [PPT][NH];
    float h1[PPT][NH];

    dense_kp<2>(sw_, KP_W0, KP_B0, xin, h);
    dense_kp<5>(sw_, KP_W1, KP_B1, h,   h);

#pragma unroll 1
    for (int l = 0; l < NL; l++) {
        dense_kp<5>(sw_, KP_R1(l), KP_B1R(l), h, h1);
        dense_res_kp(sw_, KP_W3(l), KP_W2(l), KP_B23(l), h1, h);
    }

    dense_kp<5>(sw_, KP_W8, KP_B8, h, h);

    // final [10]->[1], k-pair packed, bias folded at k2=0
    float b9 = sw_[KP_B9];
    float2 a9[PPT];
    {
        float2 w = *(const float2*)(sw_ + KP_W9);
#pragma unroll
        for (int p = 0; p < PPT; p++)
            a9[p] = ffma2(f2(h[p][0], h[p][1]), w, f2(b9, 0.0f));
    }
#pragma unroll
    for (int k2 = 1; k2 < 5; k2++) {
        float2 w = *(const float2*)(sw_ + KP_W9 + k2*2);
#pragma unroll
        for (int p = 0; p < PPT; p++)
            a9[p] = ffma2(f2(h[p][2*k2], h[p][2*k2+1]), w, a9[p]);
    }
    out4[t] = make_float4(a9[0].x + a9[0].y, a9[1].x + a9[1].y,
                          a9[2].x + a9[2].y, a9[3].x + a9[3].y);
}

extern "C" void kernel_launch(void* const* d_in, const int* in_sizes, int n_in,
                              void* d_out, int out_size)
{
    // stage raw weights into constant memory (D2D async copies: graph-capturable)
    static const int idx[14] = {1, 2, 3, 4, 5, 6, 7, 8, 9, 10, 11, 12, 13, 14};
    static const int off[14] = {OFF_W0, OFF_B0, OFF_W1, OFF_B1,
                                OFF_WR1, OFF_BR1, OFF_WR2, OFF_BR2, OFF_WR3, OFF_BR3,
                                OFF_W8, OFF_B8, OFF_W9, OFF_B9};
    static const int cnt[14] = {30, 10, 100, 10, 1000, 100, 1000, 100, 1000, 100, 100, 10, 10, 1};
    for (int i = 0; i < 14; i++) {
        cudaMemcpyToSymbolAsync(cw, d_in[idx[i]], (size_t)cnt[i] * sizeof(float),
                                (size_t)off[i] * sizeof(float),
                                cudaMemcpyDeviceToDevice, 0);
    }

    // build k-pair-packed table on device, then stage it into constant memory
    prep_kernel<<<1, 512>>>();
    void* kp_ptr = nullptr;
    cudaGetSymbolAddress(&kp_ptr, kpbuf);
    cudaMemcpyToSymbolAsync(ckp, kp_ptr, KP_TOT * sizeof(float), 0,
                            cudaMemcpyDeviceToDevice, 0);

    int npts     = in_sizes[0] / 3;   // x is [N,3]
    int nthreads = npts / PPT;        // 4 points per thread
    int nblocks  = (nthreads + TPB - 1) / TPB;
    resnet_kernel<<<nblocks, TPB>>>((const float4*)d_in[0], (float4*)d_out, nthreads);
}